// round 6
// baseline (speedup 1.0000x reference)
#include <cuda_runtime.h>
#include <math.h>

#define N_TOK 65536
#define DIM 64
#define KCODE 512
#define IN_DIM 256

typedef unsigned long long ull;

// packed fp32x2 ops (Blackwell sm_103a); each half = independent IEEE fp32 FMA
#define FMA2(d, a, b, c) \
    asm("fma.rn.f32x2 %0, %1, %2, %3;" : "=l"(d) : "l"(a), "l"(b), "l"(c))
#define PACK2(o, lo, hi) \
    asm("mov.b64 %0, {%1, %2};" : "=l"(o) : "f"(lo), "f"(hi))
#define UNPACK2(lo, hi, in) \
    asm("mov.b64 {%0, %1}, %2;" : "=f"(lo), "=f"(hi) : "l"(in))

// ---------------- device scratch (16B-aligned) ----------------
__device__ __align__(16) float g_zT[DIM * N_TOK];        // 2*z transposed [d][n]
__device__ __align__(16) float g_A[N_TOK];               // bit-exact ||z||^2
__device__ __align__(16) float g_B[KCODE];               // bit-exact ||e||^2
__device__ __align__(16) float g_eT[DIM * KCODE];        // codebook transposed
__device__ __align__(16) float g_table[KCODE * IN_DIM];  // cb @ dec_w
__device__ __align__(16) int g_idx[N_TOK];
__device__ __align__(16) unsigned int g_counts[KCODE];
__device__ __align__(16) float g_loss_part[512];

// ---------------- setup: transpose cb, zero counts, B[k] bit-exact --------
__global__ void k_setup(const float* __restrict__ cb) {
    int b = blockIdx.x, t = threadIdx.x;
    if (b < 64) {                       // transpose: eT[d][k] = cb[k][d]
        g_eT[b * KCODE + t]       = cb[(size_t)t * DIM + b];
        g_eT[b * KCODE + 256 + t] = cb[(size_t)(256 + t) * DIM + b];
    } else {                            // b == 64: counts + norms
        int k0 = t, k1 = t + 256;
        g_counts[k0] = 0u; g_counts[k1] = 0u;
        const float* e0 = cb + (size_t)k0 * DIM;
        const float* e1 = cb + (size_t)k1 * DIM;
        float s0 = 0.f, s1 = 0.f;
        for (int d = 0; d < DIM; d++) {
            s0 = __fadd_rn(s0, __fmul_rn(e0[d], e0[d]));
            s1 = __fadd_rn(s1, __fmul_rn(e1[d], e1[d]));
        }
        g_B[k0] = s0; g_B[k1] = s1;
    }
}

// ---------------- table[k][i] = sum_d cb[k][d] * dec_w[d][i] ----------------
__global__ void k_table(const float* __restrict__ cb, const float* __restrict__ dw) {
    __shared__ float e[DIM];
    int k = blockIdx.x, tid = threadIdx.x;
    if (tid < DIM) e[tid] = cb[(size_t)k * DIM + tid];
    __syncthreads();
    float acc = 0.f;
    #pragma unroll 8
    for (int d = 0; d < DIM; d++)
        acc = fmaf(e[d], dw[d * IN_DIM + tid], acc);
    g_table[(size_t)k * IN_DIM + tid] = acc;
}

// ---------------- encoder: z = x @ enc_w (bit-exact chains, FFMA2) --------
// 256 thr, 128 rows/block, x staged in 4 chunks of 64 i. 2 CTA/SM.
// Thread (rg=tid>>3, cg=tid&7): rows 4rg..+3, cols {4cg..+3, 32+4cg..+3},
// packed as 4 column-pairs per row.
#define XCH 64
#define XPC 68
__global__ void __launch_bounds__(256, 2)
k_enc(const float* __restrict__ x, const float* __restrict__ w) {
    extern __shared__ float s[];
    float* ws = s;                   // [256][64] = 64KB
    float* xs = s + IN_DIM * DIM;    // [128][XPC] = 34.8KB
    int tid = threadIdx.x;
    size_t rowbase = (size_t)blockIdx.x * 128;

    {   // w: linear float4 copy (once)
        const float4* wg = (const float4*)w;
        float4* w4 = (float4*)ws;
        #pragma unroll 4
        for (int i = tid; i < IN_DIM * DIM / 4; i += 256) w4[i] = wg[i];
    }

    int rg = tid >> 3, cg = tid & 7;
    ull acc2[4][4];                  // [row][colpair]; 0ull == (0.f,0.f)
    #pragma unroll
    for (int a = 0; a < 4; a++)
        #pragma unroll
        for (int j = 0; j < 4; j++) acc2[a][j] = 0ull;

    const float4* xg = (const float4*)(x + rowbase * IN_DIM);

    for (int c = 0; c < 4; c++) {
        __syncthreads();
        #pragma unroll
        for (int it = 0; it < 8; it++) {
            int idx = it * 256 + tid;
            int r = idx >> 4, q = idx & 15;
            *(float4*)(xs + r * XPC + 4 * q) = xg[(size_t)r * 64 + 16 * c + q];
        }
        __syncthreads();

        const float* xr0 = xs + (4 * rg + 0) * XPC;
        const float* xr1 = xs + (4 * rg + 1) * XPC;
        const float* xr2 = xs + (4 * rg + 2) * XPC;
        const float* xr3 = xs + (4 * rg + 3) * XPC;

        #pragma unroll
        for (int i4 = 0; i4 < XCH / 4; i4++) {
            float4 xv0 = *(const float4*)(xr0 + 4 * i4);
            float4 xv1 = *(const float4*)(xr1 + 4 * i4);
            float4 xv2 = *(const float4*)(xr2 + 4 * i4);
            float4 xv3 = *(const float4*)(xr3 + 4 * i4);
            #pragma unroll
            for (int j = 0; j < 4; j++) {
                int i = XCH * c + 4 * i4 + j;
                ulonglong2 wa = *(const ulonglong2*)(ws + i * DIM + 4 * cg);
                ulonglong2 wb = *(const ulonglong2*)(ws + i * DIM + 32 + 4 * cg);
                float xv[4] = {((const float*)&xv0)[j], ((const float*)&xv1)[j],
                               ((const float*)&xv2)[j], ((const float*)&xv3)[j]};
                #pragma unroll
                for (int a = 0; a < 4; a++) {
                    ull xp; PACK2(xp, xv[a], xv[a]);
                    FMA2(acc2[a][0], xp, wa.x, acc2[a][0]);
                    FMA2(acc2[a][1], xp, wa.y, acc2[a][1]);
                    FMA2(acc2[a][2], xp, wb.x, acc2[a][2]);
                    FMA2(acc2[a][3], xp, wb.y, acc2[a][3]);
                }
            }
        }
    }

    // unpack to acc[row][b], b 0..7 -> col = b<4 ? 4cg+b : 32+4cg+(b-4)
    float acc[4][8];
    #pragma unroll
    for (int a = 0; a < 4; a++)
        #pragma unroll
        for (int j = 0; j < 4; j++)
            UNPACK2(acc[a][2 * j], acc[a][2 * j + 1], acc2[a][j]);

    // store 2*z transposed (exact doubling)
    #pragma unroll
    for (int b = 0; b < 8; b++) {
        int col = (b < 4) ? (4 * cg + b) : (32 + 4 * cg + (b - 4));
        float4 v;
        v.x = 2.0f * acc[0][b]; v.y = 2.0f * acc[1][b];
        v.z = 2.0f * acc[2][b]; v.w = 2.0f * acc[3][b];
        *(float4*)(g_zT + (size_t)col * N_TOK + rowbase + 4 * rg) = v;
    }

    // A[n]: bit-exact sequential sum of z_d^2 (reuse xs region, pitch 65)
    __syncthreads();
    float* zs = xs;
    #pragma unroll
    for (int a = 0; a < 4; a++)
        #pragma unroll
        for (int b = 0; b < 8; b++) {
            int col = (b < 4) ? (4 * cg + b) : (32 + 4 * cg + (b - 4));
            zs[(4 * rg + a) * 65 + col] = acc[a][b];
        }
    __syncthreads();
    if (tid < 128) {
        const float* zr = zs + tid * 65;
        float sA = 0.f;
        for (int d = 0; d < DIM; d++)
            sA = __fadd_rn(sA, __fmul_rn(zr[d], zr[d]));
        g_A[rowbase + tid] = sA;
    }
}

// ---------------- VQ: dist = fl(fl(A+B)-m), first-index argmin, FFMA2 -----
// 512 thr, 128 tokens/block. Warp w owns tokens 8w..8w+7 (z = warp broadcast).
// Lane l, pass p in {0,1}: codes {256p+4l..+3, 256p+128+4l..+3} (ascending).
__global__ void __launch_bounds__(512, 1) k_vq() {
    extern __shared__ float s[];
    float* eT = s;                       // [64][512] = 131KB
    float* zs = s + DIM * KCODE;         // [64][128] = 32KB  (holds 2*z)
    float* Bs = zs + DIM * 128;          // [512]
    float* As = Bs + KCODE;              // [128]
    float* lred = As + 128;              // [16]
    int tid = threadIdx.x;
    size_t base = (size_t)blockIdx.x * 128;

    {   // eT: linear float4 copy
        const float4* eg = (const float4*)g_eT;
        float4* e4 = (float4*)eT;
        #pragma unroll 4
        for (int i = tid; i < DIM * KCODE / 4; i += 512) e4[i] = eg[i];
        #pragma unroll
        for (int it = 0; it < 4; it++) {
            int idx = it * 512 + tid;
            int d = idx >> 5, q = idx & 31;
            *(float4*)(zs + d * 128 + 4 * q) =
                *(const float4*)(g_zT + (size_t)d * N_TOK + base + 4 * q);
        }
        if (tid < KCODE) Bs[tid] = g_B[tid];
        if (tid < 128) As[tid] = g_A[base + tid];
    }
    __syncthreads();

    int w = tid >> 5, lane = tid & 31;
    int tok0 = 8 * w;

    float best[8]; int bidx[8];
    #pragma unroll
    for (int t = 0; t < 8; t++) { best[t] = 3.4e38f; bidx[t] = 0; }
    float Areg[8];
    #pragma unroll
    for (int t = 0; t < 8; t++) Areg[t] = As[tok0 + t];

    #pragma unroll
    for (int p = 0; p < 2; p++) {
        ull m2[8][4];
        #pragma unroll
        for (int t = 0; t < 8; t++)
            #pragma unroll
            for (int j = 0; j < 4; j++) m2[t][j] = 0ull;

        const float* ebase = eT + 256 * p + 4 * lane;
        #pragma unroll 4
        for (int d = 0; d < DIM; d++) {
            float4 za = *(const float4*)(zs + d * 128 + tok0);      // 2z, bcast
            float4 zb = *(const float4*)(zs + d * 128 + tok0 + 4);
            ulonglong2 e1 = *(const ulonglong2*)(ebase + (size_t)d * KCODE);
            ulonglong2 e2 = *(const ulonglong2*)(ebase + (size_t)d * KCODE + 128);
            float zv[8] = {za.x, za.y, za.z, za.w, zb.x, zb.y, zb.z, zb.w};
            #pragma unroll
            for (int t = 0; t < 8; t++) {
                ull zp; PACK2(zp, zv[t], zv[t]);
                FMA2(m2[t][0], zp, e1.x, m2[t][0]);
                FMA2(m2[t][1], zp, e1.y, m2[t][1]);
                FMA2(m2[t][2], zp, e2.x, m2[t][2]);
                FMA2(m2[t][3], zp, e2.y, m2[t][3]);
            }
        }
        // epilogue: ascending k within thread -> strict < = first occurrence
        #pragma unroll
        for (int j = 0; j < 4; j++) {
            int kb = 256 * p + ((j < 2) ? (4 * lane + 2 * j)
                                        : (128 + 4 * lane + 2 * (j - 2)));
            float blo = Bs[kb], bhi = Bs[kb + 1];
            #pragma unroll
            for (int t = 0; t < 8; t++) {
                float mlo, mhi;
                UNPACK2(mlo, mhi, m2[t][j]);
                float dlo = __fsub_rn(__fadd_rn(Areg[t], blo), mlo);
                float dhi = __fsub_rn(__fadd_rn(Areg[t], bhi), mhi);
                if (dlo < best[t]) { best[t] = dlo; bidx[t] = kb; }
                if (dhi < best[t]) { best[t] = dhi; bidx[t] = kb + 1; }
            }
        }
    }

    // lexicographic (dist, index) min across 32 lanes
    #pragma unroll
    for (int off = 16; off >= 1; off >>= 1) {
        #pragma unroll
        for (int t = 0; t < 8; t++) {
            float od = __shfl_xor_sync(0xffffffffu, best[t], off);
            int oi = __shfl_xor_sync(0xffffffffu, bidx[t], off);
            if (od < best[t] || (od == best[t] && oi < bidx[t])) {
                best[t] = od; bidx[t] = oi;
            }
        }
    }

    if (lane == 0) {
        float ls = 0.f;
        #pragma unroll
        for (int t = 0; t < 8; t++) {
            size_t n = base + tok0 + t;
            g_idx[n] = bidx[t];
            atomicAdd(&g_counts[bidx[t]], 1u);
            ls += best[t];          // dist == ||z - e||^2 (loose tolerance)
        }
        lred[w] = ls;
    }
    __syncthreads();
    if (tid == 0) {
        float acc = 0.f;
        #pragma unroll
        for (int t = 0; t < 16; t++) acc += lred[t];
        g_loss_part[blockIdx.x] = acc;
    }
}

// ---------------- gather: out[n][i] = table[idx[n]][i] ---------------------
__global__ void k_gather(float* __restrict__ out) {
    __shared__ int sidx[32];
    int tid = threadIdx.x;
    size_t base = (size_t)blockIdx.x * 32;
    if (tid < 32) sidx[tid] = g_idx[base + tid];
    __syncthreads();
    int rr = tid >> 6, q = tid & 63;
    #pragma unroll
    for (int j = 0; j < 8; j++) {
        int t = j * 4 + rr;
        float4 v = *(const float4*)(g_table + (size_t)sidx[t] * IN_DIM + 4 * q);
        float* o = out + (base + t) * IN_DIM + 4 * q;
        o[0] = v.x; o[1] = v.y; o[2] = v.z; o[3] = v.w;
    }
}

// ---------------- final: loss + perplexity ---------------------------------
__global__ void k_final(float* __restrict__ out, int out_size) {
    __shared__ float red[512];
    int tid = threadIdx.x;

    unsigned int cnt = g_counts[tid];
    float p = (float)cnt * (1.0f / (float)N_TOK);
    red[tid] = p * logf(p + 1e-10f);
    __syncthreads();
    for (int st = 256; st > 0; st >>= 1) {
        if (tid < st) red[tid] += red[tid + st];
        __syncthreads();
    }
    float ent = -red[0];
    __syncthreads();

    red[tid] = g_loss_part[tid];
    __syncthreads();
    for (int st = 256; st > 0; st >>= 1) {
        if (tid < st) red[tid] += red[tid + st];
        __syncthreads();
    }
    if (tid == 0) {
        out[0] = 1.25f * red[0] / (float)((size_t)N_TOK * DIM);
        out[out_size - 1] = expf(ent);
    }
}

// ---------------- launch ----------------
extern "C" void kernel_launch(void* const* d_in, const int* in_sizes, int n_in,
                              void* d_out, int out_size) {
    const float* x = nullptr;
    const float* enc_w = nullptr;
    const float* dec_w = nullptr;
    const float* cb = nullptr;
    for (int i = 0; i < n_in; i++) {
        const float* p = (const float*)d_in[i];
        int sz = in_sizes[i];
        if (sz == N_TOK * IN_DIM) x = p;
        else if (sz == KCODE * DIM) cb = p;
        else if (sz == IN_DIM * DIM) { if (!enc_w) enc_w = p; else dec_w = p; }
    }

    const int SM_ENC = (IN_DIM * DIM + 128 * XPC) * 4;                       // 100352
    const int SM_VQ  = (DIM * KCODE + DIM * 128 + KCODE + 128 + 16) * 4;     // 166464
    cudaFuncSetAttribute(k_enc, cudaFuncAttributeMaxDynamicSharedMemorySize, SM_ENC);
    cudaFuncSetAttribute(k_vq,  cudaFuncAttributeMaxDynamicSharedMemorySize, SM_VQ);

    float* out = (float*)d_out;

    k_setup<<<65, 256>>>(cb);
    k_table<<<512, 256>>>(cb, dec_w);
    k_enc<<<N_TOK / 128, 256, SM_ENC>>>(x, enc_w);
    k_vq<<<N_TOK / 128, 512, SM_VQ>>>();
    k_gather<<<N_TOK / 32, 256>>>(out + 1);
    k_final<<<1, 512>>>(out, out_size);
}